// round 9
// baseline (speedup 1.0000x reference)
#include <cuda_runtime.h>
#include <cuda_bf16.h>
#include <cstdint>

#define BB 256
#define TT 256
#define CC 1024
#define LL 64
#define SS 129          // 2L+1
#define SP 132          // padded row stride
#define RPB 4           // rows per block in emit kernel
#define NEGV (-1e30f)
#define EPSV (1e-7f)
#define FULL 0xffffffffu

// Scratch: emit log-probs, (B*T, SP) fp32  ~34.6 MB (fits L2)
__device__ float g_emit[(size_t)BB * TT * SP];

// ---------------------------------------------------------------------------
// Kernel A: 4 rows per block. Per row: sum-reduce (lse = log(sum+C*eps)),
// gather 129 extended-label log-probs into g_emit.
// ---------------------------------------------------------------------------
__global__ void __launch_bounds__(256) emit_kernel(
    const float* __restrict__ y_pred,
    const int* __restrict__ y_true)
{
    int row0 = blockIdx.x * RPB;          // first (b*T+t) row
    int b    = row0 >> 8;                 // T = 256; RPB divides 256 -> same b
    int tid  = threadIdx.x;
    int w    = tid >> 5, lane = tid & 31;

    __shared__ float srow[RPB][CC];
    __shared__ float partial[8][RPB];
    __shared__ float s_lse[RPB];

    const float4* base = reinterpret_cast<const float4*>(y_pred + (size_t)row0 * CC);

    float4 v[RPB];
    #pragma unroll
    for (int r = 0; r < RPB; r++) v[r] = base[r * 256 + tid];   // MLP = 4

    float s[RPB];
    #pragma unroll
    for (int r = 0; r < RPB; r++) {
        reinterpret_cast<float4*>(srow[r])[tid] = v[r];
        s[r] = (v[r].x + v[r].y) + (v[r].z + v[r].w);
    }

    #pragma unroll
    for (int o = 16; o > 0; o >>= 1) {
        #pragma unroll
        for (int r = 0; r < RPB; r++) s[r] += __shfl_xor_sync(FULL, s[r], o);
    }
    if (lane == 0) {
        #pragma unroll
        for (int r = 0; r < RPB; r++) partial[w][r] = s[r];
    }
    __syncthreads();
    if (tid < 32) {
        float ps[RPB];
        #pragma unroll
        for (int r = 0; r < RPB; r++) ps[r] = (lane < 8) ? partial[lane][r] : 0.0f;
        #pragma unroll
        for (int o = 4; o > 0; o >>= 1) {
            #pragma unroll
            for (int r = 0; r < RPB; r++) ps[r] += __shfl_xor_sync(FULL, ps[r], o);
        }
        if (lane == 0) {
            #pragma unroll
            for (int r = 0; r < RPB; r++) s_lse[r] = __logf(ps[r] + (float)CC * EPSV);
        }
    }
    __syncthreads();

    // gather 4*129 entries
    for (int i = tid; i < RPB * SP; i += 256) {
        int r = i / SP;
        int sidx = i - r * SP;
        if (sidx < SS) {
            int label = (sidx & 1) ? y_true[b * LL + (sidx >> 1)] : (CC - 1);
            g_emit[(size_t)(row0 + r) * SP + sidx] =
                __logf(srow[r][label] + EPSV) - s_lse[r];
        }
    }
}

// ---------------------------------------------------------------------------
// Kernel B: CTC forward recursion, ONE WARP per batch. 129 states live in
// registers as 32 lanes x 5 states. Per step: 2 shuffles, no barriers.
// ---------------------------------------------------------------------------
__global__ void __launch_bounds__(32) ctc_kernel(
    const int* __restrict__ y_true,
    float* __restrict__ out)
{
    int b    = blockIdx.x;
    int lane = threadIdx.x;
    const float* em = g_emit + (size_t)b * TT * SP;
    int base = lane * 5;

    // skip flags + init alpha (t=0)
    bool skip[5];
    float a[5];
    #pragma unroll
    for (int j = 0; j < 5; j++) {
        int s = base + j;
        bool ok = false;
        if (s < SS && (s & 1)) {
            int idx = s >> 1;
            if (idx >= 1) {
                int lab = y_true[b * LL + idx];
                ok = (lab != CC - 1) && (lab != y_true[b * LL + idx - 1]);
            }
        }
        skip[j] = ok;
        a[j] = (s < 2) ? em[s] : NEGV;
    }

    // depth-2 emit prefetch (scratch lives in L2, ~250cy)
    float e1[5], e2[5];
    #pragma unroll
    for (int j = 0; j < 5; j++) {
        int s = base + j;
        e1[j] = (s < SS) ? __ldg(em + SP + s) : 0.0f;
        e2[j] = (s < SS) ? __ldg(em + 2 * SP + s) : 0.0f;
    }

    for (int t = 1; t < TT; t++) {
        float p3 = __shfl_up_sync(FULL, a[3], 1);   // state (lane-1)*5+3 = base-2
        float p4 = __shfl_up_sync(FULL, a[4], 1);   // state (lane-1)*5+4 = base-1
        if (lane == 0) { p3 = NEGV; p4 = NEGV; }

        float na[5];
        #pragma unroll
        for (int j = 0; j < 5; j++) {
            float a1 = a[j];
            float a2 = (j == 0) ? p4 : a[j - 1];
            float a3 = skip[j] ? ((j == 0) ? p3 : (j == 1) ? p4 : a[j - 2]) : NEGV;
            float m  = fmaxf(a1, fmaxf(a2, a3));
            float sum = __expf(a1 - m) + __expf(a2 - m) + __expf(a3 - m);
            na[j] = m + __logf(sum) + e1[j];
        }
        #pragma unroll
        for (int j = 0; j < 5; j++) { a[j] = na[j]; e1[j] = e2[j]; }

        if (t + 2 < TT) {
            #pragma unroll
            for (int j = 0; j < 5; j++) {
                int s = base + j;
                e2[j] = (s < SS) ? __ldg(em + (size_t)(t + 2) * SP + s) : 0.0f;
            }
        }
    }

    // states 127 (lane 25, j=2) and 128 (lane 25, j=3)
    if (lane == 25) {
        float t1 = a[2], t2 = a[3];
        float m  = fmaxf(t1, t2);
        float ll = m + __logf(__expf(t1 - m) + __expf(t2 - m));
        out[b] = -ll;
    }
}

// ---------------------------------------------------------------------------
extern "C" void kernel_launch(void* const* d_in, const int* in_sizes, int n_in,
                              void* d_out, int out_size)
{
    const int*   y_true = nullptr;
    const float* y_pred = nullptr;
    for (int i = 0; i < n_in; i++) {
        if (in_sizes[i] == BB * LL)           y_true = (const int*)d_in[i];
        else if (in_sizes[i] == BB * TT * CC) y_pred = (const float*)d_in[i];
    }
    float* out = (float*)d_out;

    emit_kernel<<<(BB * TT) / RPB, 256>>>(y_pred, y_true);
    ctc_kernel<<<BB, 32>>>(y_true, out);
}

// round 10
// speedup vs baseline: 2.4110x; 2.4110x over previous
#include <cuda_runtime.h>
#include <cuda_bf16.h>
#include <cstdint>

#define BB 256
#define TT 256
#define CC 1024
#define LL 64
#define SS 129          // 2L+1
#define SP 132          // padded row stride
#define RPB 8           // rows per block in emit kernel
#define EPSV (1e-7f)
#define FULL 0xffffffffu

// Scratch: scaled emit probs, (B*T + pad, SP) fp32  ~34.6 MB (fits L2).
// +16 rows pad so the depth-8 prefetch never reads OOB.
__device__ float g_emit[(size_t)(BB * TT + 16) * SP];

// ---------------------------------------------------------------------------
// Kernel A: 8 rows per block. Per row: sum-reduce, then gather 129
// extended-label probs scaled:  emit = 1024*(y+eps)/(sum + C*eps).
// ---------------------------------------------------------------------------
__global__ void __launch_bounds__(256) emit_kernel(
    const float* __restrict__ y_pred,
    const int* __restrict__ y_true)
{
    int row0 = blockIdx.x * RPB;          // first (b*T+t) row
    int b    = row0 >> 8;                 // T = 256; RPB divides 256 -> same b
    int tid  = threadIdx.x;
    int w    = tid >> 5, lane = tid & 31;

    __shared__ float srow[RPB][CC];
    __shared__ float partial[8][RPB];
    __shared__ float s_rinv[RPB];

    const float4* base = reinterpret_cast<const float4*>(y_pred + (size_t)row0 * CC);

    float4 v[RPB];
    #pragma unroll
    for (int r = 0; r < RPB; r++) v[r] = base[r * 256 + tid];   // MLP = 8

    float s[RPB];
    #pragma unroll
    for (int r = 0; r < RPB; r++) {
        reinterpret_cast<float4*>(srow[r])[tid] = v[r];
        s[r] = (v[r].x + v[r].y) + (v[r].z + v[r].w);
    }

    #pragma unroll
    for (int o = 16; o > 0; o >>= 1) {
        #pragma unroll
        for (int r = 0; r < RPB; r++) s[r] += __shfl_xor_sync(FULL, s[r], o);
    }
    if (lane == 0) {
        #pragma unroll
        for (int r = 0; r < RPB; r++) partial[w][r] = s[r];
    }
    __syncthreads();
    if (tid < 32) {
        float ps[RPB];
        #pragma unroll
        for (int r = 0; r < RPB; r++) ps[r] = (lane < 8) ? partial[lane][r] : 0.0f;
        #pragma unroll
        for (int o = 4; o > 0; o >>= 1) {
            #pragma unroll
            for (int r = 0; r < RPB; r++) ps[r] += __shfl_xor_sync(FULL, ps[r], o);
        }
        if (lane == 0) {
            #pragma unroll
            for (int r = 0; r < RPB; r++)
                s_rinv[r] = __fdividef(1024.0f, ps[r] + (float)CC * EPSV);
        }
    }
    __syncthreads();

    for (int i = tid; i < RPB * SP; i += 256) {
        int r = i / SP;
        int sidx = i - r * SP;
        if (sidx < SS) {
            int label = (sidx & 1) ? y_true[b * LL + (sidx >> 1)] : (CC - 1);
            g_emit[(size_t)(row0 + r) * SP + sidx] =
                (srow[r][label] + EPSV) * s_rinv[r];
        }
    }
}

// ---------------------------------------------------------------------------
// Kernel B: CTC forward in the LINEAR domain. One warp per batch,
// 5 states/lane in registers, 2 shuffles/step, no MUFU in the loop.
// Exact power-of-2 rescale every 32 steps; emit prefetch ring depth 8.
// ---------------------------------------------------------------------------
__global__ void __launch_bounds__(32) ctc_kernel(
    const int* __restrict__ y_true,
    float* __restrict__ out)
{
    int b    = blockIdx.x;
    int lane = threadIdx.x;
    const float* em = g_emit + (size_t)b * TT * SP;
    int base = lane * 5;

    // skip flags + init alpha (t=0): alpha0 = emit0 for s<2, else 0
    bool skip[5];
    float a[5];
    #pragma unroll
    for (int j = 0; j < 5; j++) {
        int s = base + j;
        bool ok = false;
        if (s < SS && (s & 1)) {
            int idx = s >> 1;
            if (idx >= 1) {
                int lab = y_true[b * LL + idx];
                ok = (lab != CC - 1) && (lab != y_true[b * LL + idx - 1]);
            }
        }
        skip[j] = ok;
        a[j] = (s < 2) ? em[s] : 0.0f;
    }

    // emit prefetch ring: er[u] holds row t = tb + u
    float er[8][5];
    #pragma unroll
    for (int u = 0; u < 8; u++)
        #pragma unroll
        for (int j = 0; j < 5; j++)
            er[u][j] = __ldg(em + (size_t)(1 + u) * SP + base + j);

    // cross-lane carries for first step
    float p3 = __shfl_up_sync(FULL, a[3], 1);
    float p4 = __shfl_up_sync(FULL, a[4], 1);
    if (lane == 0) { p3 = 0.0f; p4 = 0.0f; }

    int SH = 0;   // accumulated power-of-2 exponent

    // main loop: t = 1 .. 248 (31 outer iters x 8)
    for (int tb = 1; tb <= 241; tb += 8) {
        #pragma unroll
        for (int u = 0; u < 8; u++) {
            // own-lane states first, then shuffle them early
            float n3 = (a[3] + a[2] + (skip[3] ? a[1] : 0.0f)) * er[u][3];
            float n4 = (a[4] + a[3] + (skip[4] ? a[2] : 0.0f)) * er[u][4];
            float q3 = __shfl_up_sync(FULL, n3, 1);
            float q4 = __shfl_up_sync(FULL, n4, 1);
            float n2 = (a[2] + a[1] + (skip[2] ? a[0] : 0.0f)) * er[u][2];
            float n0 = (a[0] + p4  + (skip[0] ? p3   : 0.0f)) * er[u][0];
            float n1 = (a[1] + a[0] + (skip[1] ? p4  : 0.0f)) * er[u][1];
            a[0] = n0; a[1] = n1; a[2] = n2; a[3] = n3; a[4] = n4;
            p3 = (lane == 0) ? 0.0f : q3;
            p4 = (lane == 0) ? 0.0f : q4;
            // prefetch row t+8 into the slot just consumed
            #pragma unroll
            for (int j = 0; j < 5; j++)
                er[u][j] = __ldg(em + (size_t)(tb + u + 8) * SP + base + j);
        }

        // exact power-of-2 rescale every 32 steps
        if ((tb & 31) == 25) {
            float mx = fmaxf(fmaxf(fmaxf(a[0], a[1]), fmaxf(a[2], a[3])), a[4]);
            #pragma unroll
            for (int o = 16; o > 0; o >>= 1)
                mx = fmaxf(mx, __shfl_xor_sync(FULL, mx, o));
            int e  = (__float_as_int(mx) >> 23) & 0xff;   // biased exponent
            int sh = 127 - e;                             // scale = 2^sh
            float sc = __int_as_float((127 + sh) << 23);
            SH += sh;
            #pragma unroll
            for (int j = 0; j < 5; j++) a[j] *= sc;
            p3 *= sc; p4 *= sc;
        }
    }

    // tail: t = 249 .. 255 (7 steps, emits already in er[0..6])
    #pragma unroll
    for (int u = 0; u < 7; u++) {
        float n3 = (a[3] + a[2] + (skip[3] ? a[1] : 0.0f)) * er[u][3];
        float n4 = (a[4] + a[3] + (skip[4] ? a[2] : 0.0f)) * er[u][4];
        float q3 = __shfl_up_sync(FULL, n3, 1);
        float q4 = __shfl_up_sync(FULL, n4, 1);
        float n2 = (a[2] + a[1] + (skip[2] ? a[0] : 0.0f)) * er[u][2];
        float n0 = (a[0] + p4  + (skip[0] ? p3   : 0.0f)) * er[u][0];
        float n1 = (a[1] + a[0] + (skip[1] ? p4  : 0.0f)) * er[u][1];
        a[0] = n0; a[1] = n1; a[2] = n2; a[3] = n3; a[4] = n4;
        p3 = (lane == 0) ? 0.0f : q3;
        p4 = (lane == 0) ? 0.0f : q4;
    }

    // states 127 (lane 25, j=2) and 128 (lane 25, j=3)
    // stored = true * 2^SH * 1024^256  ->  -loglik = -log(sum) + SH*ln2 + 256*ln1024
    if (lane == 25) {
        float sum = a[2] + a[3];
        out[b] = -logf(sum) + (float)SH * 0.69314718055994531f + 1774.4567870821627f;
    }
}

// ---------------------------------------------------------------------------
extern "C" void kernel_launch(void* const* d_in, const int* in_sizes, int n_in,
                              void* d_out, int out_size)
{
    const int*   y_true = nullptr;
    const float* y_pred = nullptr;
    for (int i = 0; i < n_in; i++) {
        if (in_sizes[i] == BB * LL)           y_true = (const int*)d_in[i];
        else if (in_sizes[i] == BB * TT * CC) y_pred = (const float*)d_in[i];
    }
    float* out = (float*)d_out;

    emit_kernel<<<(BB * TT) / RPB, 256>>>(y_pred, y_true);
    ctc_kernel<<<BB, 32>>>(y_true, out);
}

// round 11
// speedup vs baseline: 3.2810x; 1.3609x over previous
#include <cuda_runtime.h>
#include <cuda_bf16.h>
#include <cstdint>

#define BB 256
#define TT 256
#define CC 1024
#define LL 64
#define SS 129          // 2L+1
#define SP 132          // padded row stride (16B-aligned)
#define EPSV (1e-7f)
#define FULL 0xffffffffu

// Scratch: scaled emit probs, (B*T + pad, SP) fp32 ~34.6 MB (L2-resident:
// y_pred is streamed with evict-first). +16 rows pad for ring prefetch.
__device__ float g_emit[(size_t)(BB * TT + 16) * SP];

// ---------------------------------------------------------------------------
// Kernel A: warp-per-row, no block syncs. Per row: streaming load (evict-
// first), warp sum-reduce, gather 129 scaled probs:
//   emit = 1024*(y+eps)/(sum + C*eps)
// ---------------------------------------------------------------------------
__global__ void __launch_bounds__(256) emit_kernel(
    const float* __restrict__ y_pred,
    const int* __restrict__ y_true)
{
    int w    = threadIdx.x >> 5;
    int lane = threadIdx.x & 31;
    int row  = blockIdx.x * 8 + w;        // (b*T + t)
    int b    = row >> 8;                  // T = 256

    __shared__ float srow[8][CC];

    const float4* rp = reinterpret_cast<const float4*>(y_pred + (size_t)row * CC);
    float4* sp4 = reinterpret_cast<float4*>(srow[w]);

    float4 v[8];
    #pragma unroll
    for (int k = 0; k < 8; k++) v[k] = __ldcs(rp + k * 32 + lane);   // MLP=8, evict-first

    float s = 0.0f;
    #pragma unroll
    for (int k = 0; k < 8; k++) {
        sp4[k * 32 + lane] = v[k];
        s += (v[k].x + v[k].y) + (v[k].z + v[k].w);
    }
    #pragma unroll
    for (int o = 16; o > 0; o >>= 1) s += __shfl_xor_sync(FULL, s, o);

    float rinv = __fdividef(1024.0f, s + (float)CC * EPSV);
    __syncwarp();

    float* out_row = g_emit + (size_t)row * SP;
    #pragma unroll
    for (int k = 0; k < 4; k++) {
        int sidx  = k * 32 + lane;
        int label = (sidx & 1) ? y_true[b * LL + (sidx >> 1)] : (CC - 1);
        out_row[sidx] = (srow[w][label] + EPSV) * rinv;
    }
    if (lane == 0)
        out_row[128] = (srow[w][CC - 1] + EPSV) * rinv;
}

// ---------------------------------------------------------------------------
// Kernel B: linear-domain CTC forward, one warp per batch.
// State map: s = lane*4 + j (j=0..3), state 128 = j=4 on lane 31.
// Even states are blank => skip only on j=1,3; only cross-lane dep = prev n3.
// Per step: 1 shfl_up + 1 LDG.128 + 1 broadcast LDG.32, no MUFU.
// Exact power-of-2 rescale every 32 steps.
// ---------------------------------------------------------------------------
__global__ void __launch_bounds__(32) ctc_kernel(
    const int* __restrict__ y_true,
    float* __restrict__ out)
{
    int b    = blockIdx.x;
    int lane = threadIdx.x;
    const float* em = g_emit + (size_t)b * TT * SP;
    int base = lane * 4;

    // skip flags: j=1 -> label idx 2*lane, j=3 -> label idx 2*lane+1
    bool skip1 = false, skip3 = false;
    {
        int i1 = lane * 2;
        int lab1 = y_true[b * LL + i1];
        if (i1 >= 1)
            skip1 = (lab1 != CC - 1) && (lab1 != y_true[b * LL + i1 - 1]);
        int lab3 = y_true[b * LL + i1 + 1];
        skip3 = (lab3 != CC - 1) && (lab3 != lab1);
    }

    // init t=0: alpha0 = emit0 for s<2 (lane 0, j=0,1), else 0
    float a0 = 0.0f, a1 = 0.0f, a2 = 0.0f, a3 = 0.0f, a4 = 0.0f;
    if (lane == 0) { a0 = em[0]; a1 = em[1]; }

    // emit prefetch ring: er4[u] = float4 states base..base+3 of row 1+u,
    // er1[u] = state 128 of row 1+u.
    float4 er4[8]; float er1[8];
    #pragma unroll
    for (int u = 0; u < 8; u++) {
        er4[u] = *reinterpret_cast<const float4*>(em + (size_t)(1 + u) * SP + base);
        er1[u] = __ldg(em + (size_t)(1 + u) * SP + 128);
    }

    float p3 = __shfl_up_sync(FULL, a3, 1);
    if (lane == 0) p3 = 0.0f;

    int SH = 0;   // accumulated power-of-2 exponent

    // main loop: t = 1 .. 248 (31 x 8)
    for (int tb = 1; tb <= 241; tb += 8) {
        #pragma unroll
        for (int u = 0; u < 8; u++) {
            float n3 = (a3 + a2 + (skip3 ? a1 : 0.0f)) * er4[u].w;
            float q3 = __shfl_up_sync(FULL, n3, 1);
            float n0 = (a0 + p3) * er4[u].x;
            float n1 = (a1 + a0 + (skip1 ? p3 : 0.0f)) * er4[u].y;
            float n2 = (a2 + a1) * er4[u].z;
            float n4 = (a4 + a3) * er1[u];          // state 128 (lane 31)
            a0 = n0; a1 = n1; a2 = n2; a3 = n3; a4 = n4;
            p3 = (lane == 0) ? 0.0f : q3;
            // refill slot with row t+8
            er4[u] = *reinterpret_cast<const float4*>(em + (size_t)(tb + u + 8) * SP + base);
            er1[u] = __ldg(em + (size_t)(tb + u + 8) * SP + 128);
        }

        // exact power-of-2 rescale every 32 steps
        if ((tb & 31) == 25) {
            float mx = fmaxf(fmaxf(a0, a1), fmaxf(a2, fmaxf(a3, a4)));
            #pragma unroll
            for (int o = 16; o > 0; o >>= 1)
                mx = fmaxf(mx, __shfl_xor_sync(FULL, mx, o));
            int e  = (__float_as_int(mx) >> 23) & 0xff;   // biased exponent
            int sh = 127 - e;                             // scale = 2^sh
            float sc = __int_as_float((127 + sh) << 23);
            SH += sh;
            a0 *= sc; a1 *= sc; a2 *= sc; a3 *= sc; a4 *= sc;
            p3 *= sc;
        }
    }

    // tail: t = 249 .. 255 (emits already resident in er[0..6])
    #pragma unroll
    for (int u = 0; u < 7; u++) {
        float n3 = (a3 + a2 + (skip3 ? a1 : 0.0f)) * er4[u].w;
        float q3 = __shfl_up_sync(FULL, n3, 1);
        float n0 = (a0 + p3) * er4[u].x;
        float n1 = (a1 + a0 + (skip1 ? p3 : 0.0f)) * er4[u].y;
        float n2 = (a2 + a1) * er4[u].z;
        float n4 = (a4 + a3) * er1[u];
        a0 = n0; a1 = n1; a2 = n2; a3 = n3; a4 = n4;
        p3 = (lane == 0) ? 0.0f : q3;
    }

    // final: states 127 (lane31 j=3) and 128 (lane31 j=4)
    // stored = true * 2^SH * 1024^256 -> -ll = -log(sum) + SH*ln2 + 256*ln(1024)
    if (lane == 31) {
        float sum = a3 + a4;
        out[b] = -logf(sum) + (float)SH * 0.69314718055994531f + 1774.4567870821627f;
    }
}

// ---------------------------------------------------------------------------
extern "C" void kernel_launch(void* const* d_in, const int* in_sizes, int n_in,
                              void* d_out, int out_size)
{
    const int*   y_true = nullptr;
    const float* y_pred = nullptr;
    for (int i = 0; i < n_in; i++) {
        if (in_sizes[i] == BB * LL)           y_true = (const int*)d_in[i];
        else if (in_sizes[i] == BB * TT * CC) y_pred = (const float*)d_in[i];
    }
    float* out = (float*)d_out;

    emit_kernel<<<(BB * TT) / 8, 256>>>(y_pred, y_true);
    ctc_kernel<<<BB, 32>>>(y_true, out);
}

// round 16
// speedup vs baseline: 3.9779x; 1.2124x over previous
#include <cuda_runtime.h>
#include <cuda_bf16.h>
#include <cstdint>

#define BB 256
#define TT 256
#define CC 1024
#define LL 64
#define SS 129          // 2L+1
#define SP 132          // ring row stride (16B-aligned)
#define RING 16         // ring rows (power of 2)
#define NPROD 8         // producer warps
#define EPSV (1e-7f)
#define FULL 0xffffffffu

// ---------------------------------------------------------------------------
// Fused kernel: one block per batch. Warp 0 = CTC recursion consumer,
// warps 1..8 = emit producers. Emit rows flow through an SMEM ring,
// y_pred is read exactly once (evict-first). Linear-domain recursion with
// exact power-of-2 rescale every 32 steps; no MUFU in the loop.
// State map: s = lane*4 + j (j=0..3), state 128 = j=4 on lane 31.
// ---------------------------------------------------------------------------
__global__ void __launch_bounds__(32 * (NPROD + 1)) fused_ctc_kernel(
    const float* __restrict__ y_pred,
    const int* __restrict__ y_true,
    float* __restrict__ out)
{
    __shared__ float ring[RING][SP];        //  8.4 KB
    __shared__ float stage[NPROD][CC];      // 32   KB
    __shared__ int   labels[LL];
    __shared__ volatile int flags[RING];
    __shared__ volatile int cons_prog;

    int tid  = threadIdx.x;
    int w    = tid >> 5;
    int lane = tid & 31;
    int b    = blockIdx.x;

    if (tid < RING) flags[tid] = -1;
    if (tid == 0)   cons_prog  = -1;
    if (tid < LL)   labels[tid] = y_true[b * LL + tid];
    __syncthreads();

    if (w == 0) {
        // ================= CONSUMER: CTC forward recursion =================
        bool skip1, skip3;
        {
            int i1  = lane * 2;
            int lb1 = labels[i1];
            skip1 = (i1 >= 1) && (lb1 != CC - 1) && (lb1 != labels[i1 - 1]);
            int lb3 = labels[i1 + 1];
            skip3 = (lb3 != CC - 1) && (lb3 != lb1);
        }

        // t = 0 init
        while (flags[0] != 0) __nanosleep(32);
        __threadfence_block();
        float a0 = 0.f, a1 = 0.f, a2 = 0.f, a3 = 0.f, a4 = 0.f;
        if (lane == 0) { a0 = ring[0][0]; a1 = ring[0][1]; }
        float p3 = 0.0f;
        int   SH = 0;

        // t = 1..7 : per-step waits
        for (int t = 1; t < 8; t++) {
            while (flags[t] != t) __nanosleep(32);
            __threadfence_block();
            float4 e4 = *reinterpret_cast<float4*>(&ring[t][lane * 4]);
            float  e1 = ring[t][128];
            float n3 = (a3 + a2 + (skip3 ? a1 : 0.0f)) * e4.w;
            float q3 = __shfl_up_sync(FULL, n3, 1);
            float n0 = (a0 + p3) * e4.x;
            float n1 = (a1 + a0 + (skip1 ? p3 : 0.0f)) * e4.y;
            float n2 = (a2 + a1) * e4.z;
            float n4 = (a4 + a3) * e1;
            a0 = n0; a1 = n1; a2 = n2; a3 = n3; a4 = n4;
            p3 = (lane == 0) ? 0.0f : q3;
        }
        if (lane == 0) cons_prog = 7;
        __syncwarp();

        // chunks of 8: t = 8..255
        for (int c = 1; c < 32; c++) {
            int base = c * 8;
            // wait for all 8 flags of this chunk
            for (;;) {
                bool ok = true;
                if (lane < 8) ok = (flags[(base + lane) & (RING - 1)] == base + lane);
                if (__all_sync(FULL, ok)) break;
                __nanosleep(40);
            }
            __threadfence_block();

            float4 e4[8]; float e1[8];
            #pragma unroll
            for (int u = 0; u < 8; u++) {
                int slot = (base + u) & (RING - 1);
                e4[u] = *reinterpret_cast<float4*>(&ring[slot][lane * 4]);
                e1[u] = ring[slot][128];
            }
            #pragma unroll
            for (int u = 0; u < 8; u++) {
                float n3 = (a3 + a2 + (skip3 ? a1 : 0.0f)) * e4[u].w;
                float q3 = __shfl_up_sync(FULL, n3, 1);
                float n0 = (a0 + p3) * e4[u].x;
                float n1 = (a1 + a0 + (skip1 ? p3 : 0.0f)) * e4[u].y;
                float n2 = (a2 + a1) * e4[u].z;
                float n4 = (a4 + a3) * e1[u];
                a0 = n0; a1 = n1; a2 = n2; a3 = n3; a4 = n4;
                p3 = (lane == 0) ? 0.0f : q3;
            }
            if (lane == 0) cons_prog = base + 7;

            // exact power-of-2 rescale every 32 steps
            if ((c & 3) == 3) {
                float mx = fmaxf(fmaxf(a0, a1), fmaxf(a2, fmaxf(a3, a4)));
                #pragma unroll
                for (int o = 16; o > 0; o >>= 1)
                    mx = fmaxf(mx, __shfl_xor_sync(FULL, mx, o));
                int e  = (__float_as_int(mx) >> 23) & 0xff;
                int sh = 127 - e;
                float sc = __int_as_float((127 + sh) << 23);
                SH += sh;
                a0 *= sc; a1 *= sc; a2 *= sc; a3 *= sc; a4 *= sc;
                p3 *= sc;
            }
        }

        // states 127 (lane 31, j=3) and 128 (lane 31, j=4).
        // stored = true * 2^SH * 1024^256
        if (lane == 31) {
            float sum = a3 + a4;
            out[b] = -logf(sum) + (float)SH * 0.69314718055994531f
                                + 1774.4567870821627f;
        }
    } else {
        // ================= PRODUCERS: emit rows, stride NPROD ==============
        float* st = stage[w - 1];
        const float4* yp = reinterpret_cast<const float4*>(y_pred + (size_t)b * TT * CC);

        int t0 = w - 1;
        float4 v[8];
        #pragma unroll
        for (int k = 0; k < 8; k++)
            v[k] = __ldcs(yp + t0 * 256 + k * 32 + lane);

        for (int t = t0; t < TT; t += NPROD) {
            // drain current row into stage + partial sum
            float s = 0.0f;
            #pragma unroll
            for (int k = 0; k < 8; k++) {
                reinterpret_cast<float4*>(st)[k * 32 + lane] = v[k];
                s += (v[k].x + v[k].y) + (v[k].z + v[k].w);
            }
            // issue next row's loads early (overlap with gather below)
            int tn = t + NPROD;
            if (tn < TT) {
                #pragma unroll
                for (int k = 0; k < 8; k++)
                    v[k] = __ldcs(yp + tn * 256 + k * 32 + lane);
            }
            #pragma unroll
            for (int o = 16; o > 0; o >>= 1) s += __shfl_xor_sync(FULL, s, o);
            float rinv = __fdividef(1024.0f, s + (float)CC * EPSV);
            __syncwarp();

            float g[4];
            #pragma unroll
            for (int k = 0; k < 4; k++) {
                int sidx  = k * 32 + lane;
                int label = (sidx & 1) ? labels[sidx >> 1] : (CC - 1);
                g[k] = (st[label] + EPSV) * rinv;
            }
            float g128 = (st[CC - 1] + EPSV) * rinv;

            // backpressure: slot t&15 is free once row t-16 is consumed
            while (cons_prog < t - RING) __nanosleep(60);

            int slot = t & (RING - 1);
            #pragma unroll
            for (int k = 0; k < 4; k++)
                ring[slot][k * 32 + lane] = g[k];
            if (lane == 0) ring[slot][128] = g128;
            __syncwarp();
            __threadfence_block();
            if (lane == 0) flags[slot] = t;
            __syncwarp();
        }
    }
}

// ---------------------------------------------------------------------------
extern "C" void kernel_launch(void* const* d_in, const int* in_sizes, int n_in,
                              void* d_out, int out_size)
{
    const int*   y_true = nullptr;
    const float* y_pred = nullptr;
    for (int i = 0; i < n_in; i++) {
        if (in_sizes[i] == BB * LL)           y_true = (const int*)d_in[i];
        else if (in_sizes[i] == BB * TT * CC) y_pred = (const float*)d_in[i];
    }
    float* out = (float*)d_out;

    fused_ctc_kernel<<<BB, 32 * (NPROD + 1)>>>(y_pred, y_true, out);
}

// round 17
// speedup vs baseline: 5.0259x; 1.2635x over previous
#include <cuda_runtime.h>
#include <cuda_bf16.h>
#include <cstdint>

#define BB 256
#define TT 256
#define CC 1024
#define LL 64
#define RING 16         // ring rows (power of 2)
#define RW 68           // ring row stride: 64 odd emits + blank + pad
#define NPROD 8         // producer warps
#define EPSV (1e-7f)
#define FULL 0xffffffffu

// ---------------------------------------------------------------------------
// Fused CTC: one block per batch. Warp 0 = recursion consumer, warps 1..8 =
// emit producers. No SMEM staging of the prob row: sum from registers,
// gather the 65 needed values by direct LDG (L1 hits on just-streamed lines).
// Ring rows hold only the 64 odd-state (label) emits + the blank emit;
// all even states and state 128 use the blank scalar.
// Linear-domain recursion, exact power-of-2 rescale every 32 steps, no MUFU.
// State map: s = lane*4 + j (j=0..3), state 128 = j=4 on lane 31.
// ---------------------------------------------------------------------------
__global__ void __launch_bounds__(32 * (NPROD + 1)) fused_ctc_kernel(
    const float* __restrict__ y_pred,
    const int* __restrict__ y_true,
    float* __restrict__ out)
{
    __shared__ float ring[RING][RW];        // 4.3 KB
    __shared__ int   labels[LL];
    __shared__ volatile int flags[RING];
    __shared__ volatile int cons_prog;

    int tid  = threadIdx.x;
    int w    = tid >> 5;
    int lane = tid & 31;
    int b    = blockIdx.x;

    if (tid < RING) flags[tid] = -1;
    if (tid == 0)   cons_prog  = -1;
    if (tid < LL)   labels[tid] = y_true[b * LL + tid];
    __syncthreads();

    if (w == 0) {
        // ================= CONSUMER: CTC forward recursion =================
        bool skip1, skip3;
        {
            int i1  = lane * 2;
            int lb1 = labels[i1];
            skip1 = (i1 >= 1) && (lb1 != CC - 1) && (lb1 != labels[i1 - 1]);
            int lb3 = labels[i1 + 1];
            skip3 = (lb3 != CC - 1) && (lb3 != lb1);
        }

        // t = 0 init: s=0 -> blank emit, s=1 -> first label emit (lane 0)
        while (flags[0] != 0) __nanosleep(32);
        __threadfence_block();
        float a0 = 0.f, a1 = 0.f, a2 = 0.f, a3 = 0.f, a4 = 0.f;
        if (lane == 0) { a0 = ring[0][64]; a1 = ring[0][0]; }
        float p3 = 0.0f;
        int   SH = 0;

        // t = 1..7 : per-step waits
        for (int t = 1; t < 8; t++) {
            while (flags[t] != t) __nanosleep(32);
            __threadfence_block();
            float2 e  = *reinterpret_cast<float2*>(&ring[t][lane * 2]);
            float  bl = ring[t][64];
            float n3 = (a3 + a2 + (skip3 ? a1 : 0.0f)) * e.y;
            float q3 = __shfl_up_sync(FULL, n3, 1);
            float n0 = (a0 + p3) * bl;
            float n1 = (a1 + a0 + (skip1 ? p3 : 0.0f)) * e.x;
            float n2 = (a2 + a1) * bl;
            float n4 = (a4 + a3) * bl;
            a0 = n0; a1 = n1; a2 = n2; a3 = n3; a4 = n4;
            p3 = (lane == 0) ? 0.0f : q3;
        }
        if (lane == 0) cons_prog = 7;
        __syncwarp();

        // chunks of 8: t = 8..255
        for (int c = 1; c < 32; c++) {
            int base = c * 8;
            for (;;) {
                bool ok = true;
                if (lane < 8) ok = (flags[(base + lane) & (RING - 1)] == base + lane);
                if (__all_sync(FULL, ok)) break;
                __nanosleep(40);
            }
            __threadfence_block();

            float2 e[8]; float bl[8];
            #pragma unroll
            for (int u = 0; u < 8; u++) {
                int slot = (base + u) & (RING - 1);
                e[u]  = *reinterpret_cast<float2*>(&ring[slot][lane * 2]);
                bl[u] = ring[slot][64];
            }
            #pragma unroll
            for (int u = 0; u < 8; u++) {
                float n3 = (a3 + a2 + (skip3 ? a1 : 0.0f)) * e[u].y;
                float q3 = __shfl_up_sync(FULL, n3, 1);
                float n0 = (a0 + p3) * bl[u];
                float n1 = (a1 + a0 + (skip1 ? p3 : 0.0f)) * e[u].x;
                float n2 = (a2 + a1) * bl[u];
                float n4 = (a4 + a3) * bl[u];
                a0 = n0; a1 = n1; a2 = n2; a3 = n3; a4 = n4;
                p3 = (lane == 0) ? 0.0f : q3;
            }
            if (lane == 0) cons_prog = base + 7;

            // exact power-of-2 rescale every 32 steps
            if ((c & 3) == 3) {
                float mx = fmaxf(fmaxf(a0, a1), fmaxf(a2, fmaxf(a3, a4)));
                #pragma unroll
                for (int o = 16; o > 0; o >>= 1)
                    mx = fmaxf(mx, __shfl_xor_sync(FULL, mx, o));
                int e2 = (__float_as_int(mx) >> 23) & 0xff;
                int sh = 127 - e2;
                float sc = __int_as_float((127 + sh) << 23);
                SH += sh;
                a0 *= sc; a1 *= sc; a2 *= sc; a3 *= sc; a4 *= sc;
                p3 *= sc;
            }
        }

        // final: s=127 (lane31 j=3), s=128 (lane31 j=4)
        // stored = true * 2^SH * 1024^256
        if (lane == 31) {
            float sum = a3 + a4;
            out[b] = -logf(sum) + (float)SH * 0.69314718055994531f
                                + 1774.4567870821627f;
        }
    } else {
        // ================= PRODUCERS: emit rows, stride NPROD ==============
        const float* yb = y_pred + (size_t)b * TT * CC;
        int lab0 = labels[lane * 2];
        int lab1 = labels[lane * 2 + 1];

        int t0 = w - 1;
        const float4* rp = reinterpret_cast<const float4*>(yb + (size_t)t0 * CC);
        float4 v[8];
        #pragma unroll
        for (int k = 0; k < 8; k++) v[k] = rp[k * 32 + lane];

        for (int t = t0; t < TT; t += NPROD) {
            // sum current row from registers
            float s = 0.0f;
            #pragma unroll
            for (int k = 0; k < 8; k++)
                s += (v[k].x + v[k].y) + (v[k].z + v[k].w);

            // gather the 65 needed values straight from L1 (row just streamed)
            const float* yr = yb + (size_t)t * CC;
            float g0 = __ldg(yr + lab0);
            float g1 = __ldg(yr + lab1);
            float gb = __ldg(yr + (CC - 1));

            // prefetch next row
            int tn = t + NPROD;
            if (tn < TT) {
                const float4* rpn = reinterpret_cast<const float4*>(yb + (size_t)tn * CC);
                #pragma unroll
                for (int k = 0; k < 8; k++) v[k] = rpn[k * 32 + lane];
            }

            #pragma unroll
            for (int o = 16; o > 0; o >>= 1) s += __shfl_xor_sync(FULL, s, o);
            float rinv = __fdividef(1024.0f, s + (float)CC * EPSV);

            float o0 = (g0 + EPSV) * rinv;
            float o1 = (g1 + EPSV) * rinv;
            float blv = (gb + EPSV) * rinv;

            // backpressure: slot free once row t-16 consumed
            while (cons_prog < t - RING) __nanosleep(60);

            int slot = t & (RING - 1);
            *reinterpret_cast<float2*>(&ring[slot][lane * 2]) = make_float2(o0, o1);
            if (lane == 0) ring[slot][64] = blv;
            __syncwarp();
            __threadfence_block();
            if (lane == 0) flags[slot] = t;
            __syncwarp();
        }
    }
}

// ---------------------------------------------------------------------------
extern "C" void kernel_launch(void* const* d_in, const int* in_sizes, int n_in,
                              void* d_out, int out_size)
{
    const int*   y_true = nullptr;
    const float* y_pred = nullptr;
    for (int i = 0; i < n_in; i++) {
        if (in_sizes[i] == BB * LL)           y_true = (const int*)d_in[i];
        else if (in_sizes[i] == BB * TT * CC) y_pred = (const float*)d_in[i];
    }
    float* out = (float*)d_out;

    fused_ctc_kernel<<<BB, 32 * (NPROD + 1)>>>(y_pred, y_true, out);
}